// round 16
// baseline (speedup 1.0000x reference)
#include <cuda_runtime.h>
#include <cuda_fp16.h>
#include <math.h>
#include <stdint.h>

#define Bsz   64
#define Tlen  256
#define Din   128
#define Hd    1024
#define Ld    5
#define Cd    10
#define FourH 4096
#define Mrows (Tlen * Bsz)   // 16384
#define BHd   (Bsz * Hd)

// ---------------- scratch (static device globals; no allocs) ----------------
// xproj layout is GATE-INTERLEAVED: xproj[row][hcol][gate], gate order i,f,g,o
__device__ float  g_xproj[(size_t)Mrows * FourH];   // 256 MB (fp32 accumulators)
__device__ __half g_hseq0[(size_t)Mrows * Hd];      // 32 MB (fp16 h sequence)
__device__ __half g_hseq1[(size_t)Mrows * Hd];      // 32 MB
__device__ float  g_hfull[BHd];                     // full precision final h (head)
__device__ __half g_hr0[BHd];                       // fp16 h ping-pong (last layer)
__device__ __half g_hr1[BHd];
__device__ __half g_xh[(size_t)Bsz * Tlen * Din];           // fp16 x
__device__ __half g_wtf[(size_t)(Din + 4 * Hd) * FourH];    // fp16 TRANSPOSED Wx0|Wxs
__device__ unsigned g_sync[128 * 32];   // per-block epoch flags (128B strided)

// ---------------- PTX helpers ----------------
__device__ __forceinline__ uint32_t packh2(float lo, float hi) {
    __half2 h = __floats2half2_rn(lo, hi);
    return *reinterpret_cast<uint32_t*>(&h);
}
__device__ __forceinline__ void ldsm_x4(uint32_t& r0, uint32_t& r1, uint32_t& r2,
                                        uint32_t& r3, uint32_t addr) {
    asm volatile("ldmatrix.sync.aligned.m8n8.x4.shared.b16 {%0,%1,%2,%3}, [%4];"
                 : "=r"(r0), "=r"(r1), "=r"(r2), "=r"(r3) : "r"(addr));
}
__device__ __forceinline__ void mma_f16(float* d, uint32_t a0, uint32_t a1,
                                        uint32_t a2, uint32_t a3,
                                        uint32_t b0, uint32_t b1) {
    asm volatile("mma.sync.aligned.m16n8k16.row.col.f32.f16.f16.f32 "
                 "{%0,%1,%2,%3}, {%4,%5,%6,%7}, {%8,%9}, {%0,%1,%2,%3};"
                 : "+f"(d[0]), "+f"(d[1]), "+f"(d[2]), "+f"(d[3])
                 : "r"(a0), "r"(a1), "r"(a2), "r"(a3), "r"(b0), "r"(b1));
}
__device__ __forceinline__ void cp16(uint32_t dst, const void* src) {
    asm volatile("cp.async.cg.shared.global [%0], [%1], 16;" :: "r"(dst), "l"(src));
}
__device__ __forceinline__ void cp_commit() {
    asm volatile("cp.async.commit_group;");
}
template <int N>
__device__ __forceinline__ void cp_wait() {
    asm volatile("cp.async.wait_group %0;" :: "n"(N));
}
__device__ __forceinline__ void bar_sync(int id, int cnt) {
    asm volatile("bar.sync %0, %1;" :: "r"(id), "r"(cnt) : "memory");
}

// ---------------- grid barrier: all-to-all flag scan ----------------
__device__ __forceinline__ void grid_sync(unsigned epoch) {
    __syncthreads();
    if (threadIdx.x == 0) {
        __threadfence();
        asm volatile("st.release.gpu.global.u32 [%0], %1;"
                     :: "l"(&g_sync[blockIdx.x * 32]), "r"(epoch) : "memory");
    }
    if (threadIdx.x < 128) {
        unsigned v;
        do {
            asm volatile("ld.acquire.gpu.global.u32 %0, [%1];"
                         : "=r"(v) : "l"(&g_sync[threadIdx.x * 32]) : "memory");
        } while (v < epoch);
    }
    __syncthreads();
}

// ---------------- fast activations ----------------
__device__ __forceinline__ float sigmoid_f(float x) {
    return __fdividef(1.f, 1.f + __expf(-x));
}
__device__ __forceinline__ float tanh_f(float x) {
    float e = __expf(2.f * x);
    return 1.f - __fdividef(2.f, e + 1.f);
}

// ---------------- prep kernels ----------------
__global__ void preround_x(const float* __restrict__ x) {
    // also resets the grid-barrier flags (replay-safe: epochs restart each replay)
    if (blockIdx.x == 0 && threadIdx.x < 128)
        g_sync[threadIdx.x * 32] = 0u;
    size_t nx = (size_t)Bsz * Tlen * Din;
    size_t stride = (size_t)gridDim.x * blockDim.x;
    for (size_t i = (size_t)blockIdx.x * blockDim.x + threadIdx.x; i < nx; i += stride)
        g_xh[i] = __float2half_rn(x[i]);
}

// transpose + fp16 round ALL input weights: rows 0..3 -> Wx0, rest -> Wxs
__global__ void transpose_all(const float* __restrict__ Wx0,
                              const float* __restrict__ Wxs)
{
    __shared__ float tile[32][33];
    int yb = blockIdx.y;
    int nb = blockIdx.x * 32;
    int tx = threadIdx.x, ty = threadIdx.y;
    if (yb < Din / 32) {
        int kb = yb * 32;
        for (int i = ty; i < 32; i += 8)
            tile[i][tx] = Wx0[(size_t)(kb + i) * FourH + nb + tx];
        __syncthreads();
        for (int i = ty; i < 32; i += 8)
            g_wtf[(size_t)(nb + i) * Din + kb + tx] = __float2half_rn(tile[tx][i]);
    } else {
        int kg = (yb - Din / 32) * 32;       // 0..4095 across 4 matrices
        int mat = kg >> 10;
        int kb  = kg & 1023;
        const float* s = Wxs + (size_t)mat * Hd * FourH;
        __half* d = g_wtf + (size_t)Din * FourH + (size_t)mat * Hd * FourH;
        for (int i = ty; i < 32; i += 8)
            tile[i][tx] = s[(size_t)(kb + i) * FourH + nb + tx];
        __syncthreads();
        for (int i = ty; i < 32; i += 8)
            d[(size_t)(nb + i) * Hd + kb + tx] = __float2half_rn(tile[tx][i]);
    }
}

// ============================================================================
// Input projection GEMM (fp16 mma m16n8k16, cp.async 3-stage pipeline)
//   Block tile 128(M) x 256(N), k-tile 32 halves, 512 threads = 16 warps (2m x 8n).
// ============================================================================
#define PPITCH 40
#define PSLOT_A (128 * PPITCH * 2)         // 10240 B
#define PSLOT_B (256 * PPITCH * 2)         // 20480 B
#define PSLOT   (PSLOT_A + PSLOT_B)        // 30720 B
#define PROJ_SMEM (3 * PSLOT)              // 92160 B

__global__ __launch_bounds__(512) void proj_gemm_tc(
    const __half* __restrict__ A, int stride_t, int stride_b, int K,
    const __half* __restrict__ Wt, const float* __restrict__ bias)
{
    extern __shared__ char psb[];
    uint32_t sbase = (uint32_t)__cvta_generic_to_shared(psb);

    int tid  = threadIdx.x;
    int wid  = tid >> 5;
    int lane = tid & 31;
    int row0 = blockIdx.y * 128;
    int col0 = blockIdx.x * 256;

    int wm = wid & 1;          // m-group (64 rows)
    int wn = wid >> 1;         // n-group (32 cols)

    int a_row = tid >> 2;
    int a_seg = tid & 3;
    int agrow = row0 + a_row;
    const __half* Aptr = A + (size_t)(agrow >> 6) * stride_t
                           + (size_t)(agrow & 63) * stride_b;

    int l_r8 = lane & 7;
    int l_m1 = (lane >> 3) & 1;
    int l_m2 = lane >> 4;

    float acc[4][4][4];
#pragma unroll
    for (int i = 0; i < 4; i++)
#pragma unroll
        for (int j = 0; j < 4; j++)
#pragma unroll
            for (int r = 0; r < 4; r++) acc[i][j][r] = 0.f;

    int ntiles = K >> 5;

    auto issue = [&](int stage, int kt) {
        if (kt < ntiles) {
            int kb = kt * 32;
            uint32_t sa = sbase + stage * PSLOT;
            cp16(sa + (a_row * PPITCH + a_seg * 8) * 2, Aptr + kb + a_seg * 8);
            uint32_t sb = sa + PSLOT_A;
#pragma unroll
            for (int i = 0; i < 2; i++) {
                int id = i * 512 + tid;
                int n = id >> 2, seg = id & 3;
                cp16(sb + (n * PPITCH + seg * 8) * 2,
                     Wt + (size_t)(col0 + n) * K + kb + seg * 8);
            }
        }
        cp_commit();
    };

    issue(0, 0);
    issue(1, 1);

    for (int kt = 0; kt < ntiles; kt++) {
        cp_wait<1>();
        __syncthreads();
        int cur = kt % 3;
        issue((kt + 2) % 3, kt + 2);

        uint32_t asb = sbase + cur * PSLOT;
        uint32_t bsb = asb + PSLOT_A;

#pragma unroll
        for (int kk = 0; kk < 2; kk++) {
            uint32_t bf[4][2];
#pragma unroll
            for (int ntq = 0; ntq < 2; ntq++) {
                int n_row = wn * 32 + ntq * 16 + l_r8 + l_m2 * 8;
                int k_off = kk * 16 + l_m1 * 8;
                ldsm_x4(bf[2 * ntq][0], bf[2 * ntq][1],
                        bf[2 * ntq + 1][0], bf[2 * ntq + 1][1],
                        bsb + (n_row * PPITCH + k_off) * 2);
            }
#pragma unroll
            for (int mt = 0; mt < 4; mt++) {
                int ar = wm * 64 + mt * 16 + l_r8 + l_m1 * 8;
                int ak = kk * 16 + l_m2 * 8;
                uint32_t a0, a1, a2, a3;
                ldsm_x4(a0, a1, a2, a3, asb + (ar * PPITCH + ak) * 2);
#pragma unroll
                for (int nt = 0; nt < 4; nt++)
                    mma_f16(acc[mt][nt], a0, a1, a2, a3, bf[nt][0], bf[nt][1]);
            }
        }
    }

    // epilogue: add bias, store gate-interleaved (fp32)
    int gate  = col0 >> 10;
    int hbase = col0 & 1023;
#pragma unroll
    for (int mt = 0; mt < 4; mt++) {
        int row = row0 + wm * 64 + mt * 16 + (lane >> 2);
#pragma unroll
        for (int nt = 0; nt < 4; nt++) {
            int nl = wn * 32 + nt * 8 + 2 * (lane & 3);
            float b0v = bias[col0 + nl];
            float b1v = bias[col0 + nl + 1];
            int hcol = hbase + nl;
            float* o0 = g_xproj + (size_t)row * FourH + hcol * 4 + gate;
            o0[0] = acc[mt][nt][0] + b0v;
            o0[4] = acc[mt][nt][1] + b1v;
            float* o1 = o0 + (size_t)8 * FourH;
            o1[0] = acc[mt][nt][2] + b0v;
            o1[4] = acc[mt][nt][3] + b1v;
        }
    }
}

// ============================================================================
// Persistent recurrent layer (fp16; FULL k-range staged per step, 2 chunks)
//   128 blocks x 512 threads; 16 warps = (gate g = wid&3) x (k-split s = wid>>2)
//   Group s stages its whole k-range [s*256, s*256+256) as 2 committed chunks;
//   mma loop has only 2 sync points per step (after chunk A, after chunk B).
//   Staged pitch 264 halves (528 B) -> conflict-free ldmatrix phases.
// ============================================================================
#define RPH     264                      // staged pitch (halves) per row
#define GSEG    (64 * RPH * 2)           // 33792 B per group
#define PD_OFF  (4 * GSEG)               // 135168 B
#define PDPITCH 36
#define PDSEG   (64 * PDPITCH)
#define REC_SMEM (PD_OFF + 4 * PDSEG * 4)   // 172032 B

__global__ __launch_bounds__(512) void lstm_layer_tc(
    const float* __restrict__ Wh, int seqsel, int writeseq, unsigned epoch0)
{
    extern __shared__ char rsb[];
    float* pD = (float*)(rsb + PD_OFF);
    uint32_t sbase = (uint32_t)__cvta_generic_to_shared(rsb);

    int tid  = threadIdx.x;
    int wid  = tid >> 5;
    int lane = tid & 31;
    int g    = wid & 3;
    int s    = wid >> 2;       // == tid >> 7 : k-split group
    int c0   = blockIdx.x * 8;

    // ---- Wh slice into registers as fp16 B-fragments (m16n8k16) ----
    uint32_t b0[16], b1[16];
    {
        const float* Wb = Wh + (size_t)(g * Hd + c0 + (lane >> 2));
#pragma unroll
        for (int j = 0; j < 16; j++) {
            int kb2 = s * 256 + j * 16 + (lane & 3) * 2;
            b0[j] = packh2(Wb[(size_t)kb2 * FourH], Wb[(size_t)(kb2 + 1) * FourH]);
            b1[j] = packh2(Wb[(size_t)(kb2 + 8) * FourH], Wb[(size_t)(kb2 + 9) * FourH]);
        }
    }

    __half* seq = seqsel ? g_hseq1 : g_hseq0;

    // per-group staging map: 128 threads = 64 rows x 2 halves-of-range
    int srow = (tid & 127) >> 1;
    int part = tid & 1;                      // 64-half sub-chunk within each 128-chunk
    uint32_t dbase = sbase + s * GSEG + srow * (RPH * 2);

    int l_r8 = lane & 7;
    int l_m1 = (lane >> 3) & 1;
    int l_m2 = lane >> 4;

    int gm = tid >> 3, ghc = tid & 7;
    int ghi = gm * Hd + c0 + ghc;

    float creg = 0.f;
    unsigned epoch = epoch0;

    for (int t = 0; t < Tlen; t++) {
        float4 xp = *(const float4*)&g_xproj[((size_t)(t * Bsz + gm)) * FourH
                                             + (c0 + ghc) * 4];

        float acc[4][4];
#pragma unroll
        for (int mt = 0; mt < 4; mt++)
#pragma unroll
            for (int r = 0; r < 4; r++) acc[mt][r] = 0.f;

        if (t > 0) {
            const __half* hr_in = writeseq ? (seq + (size_t)(t - 1) * BHd)
                                           : ((t & 1) ? g_hr1 : g_hr0);
            const __half* hsrc = hr_in + srow * Hd + s * 256 + part * 64;

            // stage both 128-k chunks, one commit each
#pragma unroll
            for (int c = 0; c < 2; c++) {
                uint32_t dst = dbase + (c * 128 + part * 64) * 2;
#pragma unroll
                for (int j = 0; j < 8; j++)
                    cp16(dst + j * 16, hsrc + c * 128 + j * 8);
                cp_commit();
            }

            uint32_t asb = sbase + s * GSEG;

            // chunk A ready -> mma j = 0..7 (while chunk B streams in)
            cp_wait<1>();
            bar_sync(1 + s, 128);
#pragma unroll
            for (int j = 0; j < 8; j++) {
                int ak = j * 16 + l_m2 * 8;
#pragma unroll
                for (int mt = 0; mt < 4; mt++) {
                    int ar = mt * 16 + l_r8 + l_m1 * 8;
                    uint32_t a0, a1, a2, a3;
                    ldsm_x4(a0, a1, a2, a3, asb + (ar * RPH + ak) * 2);
                    mma_f16(acc[mt], a0, a1, a2, a3, b0[j], b1[j]);
                }
            }
            // chunk B ready -> mma j = 8..15
            cp_wait<0>();
            bar_sync(1 + s, 128);
#pragma unroll
            for (int j = 8; j < 16; j++) {
                int ak = j * 16 + l_m2 * 8;
#pragma unroll
                for (int mt = 0; mt < 4; mt++) {
                    int ar = mt * 16 + l_r8 + l_m1 * 8;
                    uint32_t a0, a1, a2, a3;
                    ldsm_x4(a0, a1, a2, a3, asb + (ar * RPH + ak) * 2);
                    mma_f16(acc[mt], a0, a1, a2, a3, b0[j], b1[j]);
                }
            }
        }

        // write k-split partials (per-warp private region)
#pragma unroll
        for (int mt = 0; mt < 4; mt++) {
            int row = mt * 16 + (lane >> 2);
            float* p = pD + s * PDSEG + row * PDPITCH + g * 8 + 2 * (lane & 3);
            p[0] = acc[mt][0];
            p[1] = acc[mt][1];
            p[8 * PDPITCH]     = acc[mt][2];
            p[8 * PDPITCH + 1] = acc[mt][3];
        }
        __syncthreads();

        // fused gate phase
        {
            float zi = xp.x, zf = xp.y, zg = xp.z, zo = xp.w;
#pragma unroll
            for (int spp = 0; spp < 4; spp++) {
                const float* q = pD + spp * PDSEG + gm * PDPITCH;
                zi += q[ghc];
                zf += q[8 + ghc];
                zg += q[16 + ghc];
                zo += q[24 + ghc];
            }
            float si = sigmoid_f(zi);
            float sf = sigmoid_f(zf);
            float so = sigmoid_f(zo);
            float tg = tanh_f(zg);
            float cn = sf * creg + si * tg;
            float hn = so * tanh_f(cn);
            creg = cn;
            __half hh = __float2half_rn(hn);
            if (writeseq) {
                seq[((size_t)(t * Bsz + gm)) * Hd + c0 + ghc] = hh;
            } else {
                __half* hr_out = (t & 1) ? g_hr0 : g_hr1;
                hr_out[ghi] = hh;
                if (t == Tlen - 1) g_hfull[ghi] = hn;
            }
        }
        grid_sync(++epoch);
    }
}

// ---------------- head ----------------
__global__ void head_kernel(const float* __restrict__ Wc, const float* __restrict__ bc,
                            float* __restrict__ out)
{
    int b = blockIdx.x;
    int w = threadIdx.x >> 5;
    int lane = threadIdx.x & 31;
    const float* h = g_hfull + b * Hd;
    float s = 0.f;
    for (int k = lane; k < Hd; k += 32) s += h[k] * Wc[k * Cd + w];
#pragma unroll
    for (int o = 16; o > 0; o >>= 1) s += __shfl_down_sync(0xffffffffu, s, o);
    if (lane == 0) out[b * Cd + w] = s + bc[w];
}

// ---------------- launch ----------------
extern "C" void kernel_launch(void* const* d_in, const int* in_sizes, int n_in,
                              void* d_out, int out_size)
{
    const float* x    = (const float*)d_in[0];
    const float* Wx0  = (const float*)d_in[1];
    const float* Wxs  = (const float*)d_in[2];
    const float* Whs  = (const float*)d_in[3];
    const float* bs   = (const float*)d_in[4];
    const float* Wc   = (const float*)d_in[5];
    const float* bc   = (const float*)d_in[6];
    float* out = (float*)d_out;

    cudaFuncSetAttribute(proj_gemm_tc,
                         cudaFuncAttributeMaxDynamicSharedMemorySize, PROJ_SMEM);
    cudaFuncSetAttribute(lstm_layer_tc,
                         cudaFuncAttributeMaxDynamicSharedMemorySize, REC_SMEM);

    __half* xh = nullptr; __half* wtf = nullptr;
    { void* p; cudaGetSymbolAddress(&p, g_xh); xh = (__half*)p; }
    { void* p; cudaGetSymbolAddress(&p, g_wtf); wtf = (__half*)p; }
    __half* hs0 = nullptr; __half* hs1 = nullptr;
    { void* p; cudaGetSymbolAddress(&p, g_hseq0); hs0 = (__half*)p; }
    { void* p; cudaGetSymbolAddress(&p, g_hseq1); hs1 = (__half*)p; }

    // prep: 2 launches (flags reset folded into preround_x)
    preround_x<<<512, 256>>>(x);
    transpose_all<<<dim3(FourH / 32, (Din + 4 * Hd) / 32), dim3(32, 8)>>>(Wx0, Wxs);

    dim3 pgrid(FourH / 256, Mrows / 128);   // 16 x 128

    for (int l = 0; l < Ld; l++) {
        const __half* A  = (l == 0) ? xh : (((l - 1) & 1) == 0 ? hs0 : hs1);
        const __half* Wt = (l == 0) ? wtf : (wtf + (size_t)Din * FourH
                                                + (size_t)(l - 1) * Hd * FourH);
        int K  = (l == 0) ? Din : Hd;
        int st = (l == 0) ? Din : Bsz * Hd;
        int sb = (l == 0) ? Tlen * Din : Hd;

        proj_gemm_tc<<<pgrid, 512, PROJ_SMEM>>>(A, st, sb, K, Wt,
                                                bs + (size_t)l * FourH);

        const float* Wh = Whs + (size_t)l * Hd * FourH;
        lstm_layer_tc<<<128, 512, REC_SMEM>>>(Wh, l & 1, (l < Ld - 1) ? 1 : 0,
                                              (unsigned)l * Tlen);
    }

    head_kernel<<<Bsz, 320>>>(Wc, bc, out);
}

// round 17
// speedup vs baseline: 1.3078x; 1.3078x over previous
#include <cuda_runtime.h>
#include <cuda_fp16.h>
#include <math.h>
#include <stdint.h>

#define Bsz   64
#define Tlen  256
#define Din   128
#define Hd    1024
#define Ld    5
#define Cd    10
#define FourH 4096
#define Mrows (Tlen * Bsz)   // 16384
#define BHd   (Bsz * Hd)

// ---------------- scratch (static device globals; no allocs) ----------------
// xproj layout is GATE-INTERLEAVED: xproj[row][hcol][gate], gate order i,f,g,o
__device__ float  g_xproj[(size_t)Mrows * FourH];   // 256 MB (fp32 accumulators)
__device__ __half g_hseq0[(size_t)Mrows * Hd];      // 32 MB (fp16 h sequence)
__device__ __half g_hseq1[(size_t)Mrows * Hd];      // 32 MB
__device__ float  g_hfull[BHd];                     // full precision final h (head)
__device__ __half g_hr0[BHd];                       // fp16 h ping-pong (last layer)
__device__ __half g_hr1[BHd];
__device__ __half g_xh[(size_t)Bsz * Tlen * Din];           // fp16 x
__device__ __half g_wtf[(size_t)(Din + 4 * Hd) * FourH];    // fp16 TRANSPOSED Wx0|Wxs
__device__ unsigned g_cnt[32];                      // monotonic arrival counter

// ---------------- PTX helpers ----------------
__device__ __forceinline__ uint32_t packh2(float lo, float hi) {
    __half2 h = __floats2half2_rn(lo, hi);
    return *reinterpret_cast<uint32_t*>(&h);
}
__device__ __forceinline__ void ldsm_x4(uint32_t& r0, uint32_t& r1, uint32_t& r2,
                                        uint32_t& r3, uint32_t addr) {
    asm volatile("ldmatrix.sync.aligned.m8n8.x4.shared.b16 {%0,%1,%2,%3}, [%4];"
                 : "=r"(r0), "=r"(r1), "=r"(r2), "=r"(r3) : "r"(addr));
}
__device__ __forceinline__ void mma_f16(float* d, uint32_t a0, uint32_t a1,
                                        uint32_t a2, uint32_t a3,
                                        uint32_t b0, uint32_t b1) {
    asm volatile("mma.sync.aligned.m16n8k16.row.col.f32.f16.f16.f32 "
                 "{%0,%1,%2,%3}, {%4,%5,%6,%7}, {%8,%9}, {%0,%1,%2,%3};"
                 : "+f"(d[0]), "+f"(d[1]), "+f"(d[2]), "+f"(d[3])
                 : "r"(a0), "r"(a1), "r"(a2), "r"(a3), "r"(b0), "r"(b1));
}
__device__ __forceinline__ void cp16(uint32_t dst, const void* src) {
    asm volatile("cp.async.cg.shared.global [%0], [%1], 16;" :: "r"(dst), "l"(src));
}
__device__ __forceinline__ void cp_commit() {
    asm volatile("cp.async.commit_group;");
}
template <int N>
__device__ __forceinline__ void cp_wait() {
    asm volatile("cp.async.wait_group %0;" :: "n"(N));
}
__device__ __forceinline__ void bar_sync(int id, int cnt) {
    asm volatile("bar.sync %0, %1;" :: "r"(id), "r"(cnt) : "memory");
}

// ---------------- grid barrier: single monotonic counter ----------------
__device__ __forceinline__ void grid_sync(unsigned epoch) {
    __syncthreads();
    if (threadIdx.x == 0) {
        __threadfence();
        asm volatile("red.release.gpu.global.add.u32 [%0], %1;"
                     :: "l"(&g_cnt[0]), "r"(1u) : "memory");
        unsigned v, tgt = 128u * epoch;
        do {
            asm volatile("ld.acquire.gpu.global.u32 %0, [%1];"
                         : "=r"(v) : "l"(&g_cnt[0]) : "memory");
        } while (v < tgt);
    }
    __syncthreads();
}

// ---------------- fast activations ----------------
__device__ __forceinline__ float sigmoid_f(float x) {
    return __fdividef(1.f, 1.f + __expf(-x));
}
__device__ __forceinline__ float tanh_f(float x) {
    float e = __expf(2.f * x);
    return 1.f - __fdividef(2.f, e + 1.f);
}

// ---------------- prep kernels ----------------
__global__ void preround_x(const float* __restrict__ x) {
    // also resets the barrier counter (replay-safe: epochs restart each replay)
    if (blockIdx.x == 0 && threadIdx.x == 0)
        g_cnt[0] = 0u;
    size_t nx = (size_t)Bsz * Tlen * Din;
    size_t stride = (size_t)gridDim.x * blockDim.x;
    for (size_t i = (size_t)blockIdx.x * blockDim.x + threadIdx.x; i < nx; i += stride)
        g_xh[i] = __float2half_rn(x[i]);
}

// transpose + fp16 round ALL input weights: rows 0..3 -> Wx0, rest -> Wxs
__global__ void transpose_all(const float* __restrict__ Wx0,
                              const float* __restrict__ Wxs)
{
    __shared__ float tile[32][33];
    int yb = blockIdx.y;
    int nb = blockIdx.x * 32;
    int tx = threadIdx.x, ty = threadIdx.y;
    if (yb < Din / 32) {
        int kb = yb * 32;
        for (int i = ty; i < 32; i += 8)
            tile[i][tx] = Wx0[(size_t)(kb + i) * FourH + nb + tx];
        __syncthreads();
        for (int i = ty; i < 32; i += 8)
            g_wtf[(size_t)(nb + i) * Din + kb + tx] = __float2half_rn(tile[tx][i]);
    } else {
        int kg = (yb - Din / 32) * 32;       // 0..4095 across 4 matrices
        int mat = kg >> 10;
        int kb  = kg & 1023;
        const float* s = Wxs + (size_t)mat * Hd * FourH;
        __half* d = g_wtf + (size_t)Din * FourH + (size_t)mat * Hd * FourH;
        for (int i = ty; i < 32; i += 8)
            tile[i][tx] = s[(size_t)(kb + i) * FourH + nb + tx];
        __syncthreads();
        for (int i = ty; i < 32; i += 8)
            d[(size_t)(nb + i) * Hd + kb + tx] = __float2half_rn(tile[tx][i]);
    }
}

// ============================================================================
// Input projection GEMM (fp16 mma m16n8k16, cp.async 3-stage pipeline)
//   Block tile 128(M) x 256(N), k-tile 32 halves, 512 threads = 16 warps (2m x 8n).
// ============================================================================
#define PPITCH 40
#define PSLOT_A (128 * PPITCH * 2)         // 10240 B
#define PSLOT_B (256 * PPITCH * 2)         // 20480 B
#define PSLOT   (PSLOT_A + PSLOT_B)        // 30720 B
#define PROJ_SMEM (3 * PSLOT)              // 92160 B

__global__ __launch_bounds__(512) void proj_gemm_tc(
    const __half* __restrict__ A, int stride_t, int stride_b, int K,
    const __half* __restrict__ Wt, const float* __restrict__ bias)
{
    extern __shared__ char psb[];
    uint32_t sbase = (uint32_t)__cvta_generic_to_shared(psb);

    int tid  = threadIdx.x;
    int wid  = tid >> 5;
    int lane = tid & 31;
    int row0 = blockIdx.y * 128;
    int col0 = blockIdx.x * 256;

    int wm = wid & 1;          // m-group (64 rows)
    int wn = wid >> 1;         // n-group (32 cols)

    int a_row = tid >> 2;
    int a_seg = tid & 3;
    int agrow = row0 + a_row;
    const __half* Aptr = A + (size_t)(agrow >> 6) * stride_t
                           + (size_t)(agrow & 63) * stride_b;

    int l_r8 = lane & 7;
    int l_m1 = (lane >> 3) & 1;
    int l_m2 = lane >> 4;

    float acc[4][4][4];
#pragma unroll
    for (int i = 0; i < 4; i++)
#pragma unroll
        for (int j = 0; j < 4; j++)
#pragma unroll
            for (int r = 0; r < 4; r++) acc[i][j][r] = 0.f;

    int ntiles = K >> 5;

    auto issue = [&](int stage, int kt) {
        if (kt < ntiles) {
            int kb = kt * 32;
            uint32_t sa = sbase + stage * PSLOT;
            cp16(sa + (a_row * PPITCH + a_seg * 8) * 2, Aptr + kb + a_seg * 8);
            uint32_t sb = sa + PSLOT_A;
#pragma unroll
            for (int i = 0; i < 2; i++) {
                int id = i * 512 + tid;
                int n = id >> 2, seg = id & 3;
                cp16(sb + (n * PPITCH + seg * 8) * 2,
                     Wt + (size_t)(col0 + n) * K + kb + seg * 8);
            }
        }
        cp_commit();
    };

    issue(0, 0);
    issue(1, 1);

    for (int kt = 0; kt < ntiles; kt++) {
        cp_wait<1>();
        __syncthreads();
        int cur = kt % 3;
        issue((kt + 2) % 3, kt + 2);

        uint32_t asb = sbase + cur * PSLOT;
        uint32_t bsb = asb + PSLOT_A;

#pragma unroll
        for (int kk = 0; kk < 2; kk++) {
            uint32_t bf[4][2];
#pragma unroll
            for (int ntq = 0; ntq < 2; ntq++) {
                int n_row = wn * 32 + ntq * 16 + l_r8 + l_m2 * 8;
                int k_off = kk * 16 + l_m1 * 8;
                ldsm_x4(bf[2 * ntq][0], bf[2 * ntq][1],
                        bf[2 * ntq + 1][0], bf[2 * ntq + 1][1],
                        bsb + (n_row * PPITCH + k_off) * 2);
            }
#pragma unroll
            for (int mt = 0; mt < 4; mt++) {
                int ar = wm * 64 + mt * 16 + l_r8 + l_m1 * 8;
                int ak = kk * 16 + l_m2 * 8;
                uint32_t a0, a1, a2, a3;
                ldsm_x4(a0, a1, a2, a3, asb + (ar * PPITCH + ak) * 2);
#pragma unroll
                for (int nt = 0; nt < 4; nt++)
                    mma_f16(acc[mt][nt], a0, a1, a2, a3, bf[nt][0], bf[nt][1]);
            }
        }
    }

    // epilogue: add bias, store gate-interleaved (fp32)
    int gate  = col0 >> 10;
    int hbase = col0 & 1023;
#pragma unroll
    for (int mt = 0; mt < 4; mt++) {
        int row = row0 + wm * 64 + mt * 16 + (lane >> 2);
#pragma unroll
        for (int nt = 0; nt < 4; nt++) {
            int nl = wn * 32 + nt * 8 + 2 * (lane & 3);
            float b0v = bias[col0 + nl];
            float b1v = bias[col0 + nl + 1];
            int hcol = hbase + nl;
            float* o0 = g_xproj + (size_t)row * FourH + hcol * 4 + gate;
            o0[0] = acc[mt][nt][0] + b0v;
            o0[4] = acc[mt][nt][1] + b1v;
            float* o1 = o0 + (size_t)8 * FourH;
            o1[0] = acc[mt][nt][2] + b0v;
            o1[4] = acc[mt][nt][3] + b1v;
        }
    }
}

// ============================================================================
// Persistent recurrent layer (R15 mainloop verbatim; counter barrier + xp pipe)
//   128 blocks x 512 threads; 16 warps = (gate g = wid&3) x (k-split s = wid>>2)
//   Group s stages its k-range [s*256, s*256+256) via 4-stage ring of 32-k
//   tiles; kt loop syncs with bar.sync(1+s, 128).
// ============================================================================
#define RPH     40                       // staged pitch (halves)
#define RSEG_B  (64 * RPH * 2)           // 5120 B per split per tile
#define KTF_B   (4 * RSEG_B)             // 20480 B per staged tile
#define NSTG    4
#define PDPITCH 36
#define PDSEG   (64 * PDPITCH)
#define REC_SMEM (NSTG * KTF_B + 4 * PDSEG * 4)   // 118784 B

__global__ __launch_bounds__(512) void lstm_layer_tc(
    const float* __restrict__ Wh, int seqsel, int writeseq, unsigned epoch0)
{
    extern __shared__ char rsb[];
    float* pD = (float*)(rsb + NSTG * KTF_B);
    uint32_t sbase = (uint32_t)__cvta_generic_to_shared(rsb);

    int tid  = threadIdx.x;
    int wid  = tid >> 5;
    int lane = tid & 31;
    int g    = wid & 3;
    int s    = wid >> 2;       // == tid >> 7 : k-split group
    int c0   = blockIdx.x * 8;

    // ---- Wh slice into registers as fp16 B-fragments (m16n8k16) ----
    uint32_t b0[16], b1[16];
    {
        const float* Wb = Wh + (size_t)(g * Hd + c0 + (lane >> 2));
#pragma unroll
        for (int j = 0; j < 16; j++) {
            int kb2 = s * 256 + j * 16 + (lane & 3) * 2;
            b0[j] = packh2(Wb[(size_t)kb2 * FourH], Wb[(size_t)(kb2 + 1) * FourH]);
            b1[j] = packh2(Wb[(size_t)(kb2 + 8) * FourH], Wb[(size_t)(kb2 + 9) * FourH]);
        }
    }

    __half* seq = seqsel ? g_hseq1 : g_hseq0;

    // per-group staging map: 128 threads cover 64 rows x 32 halves (2 thr/row)
    int srow = (tid & 127) >> 1;
    int part = tid & 1;
    uint32_t dbase = sbase + s * RSEG_B + srow * (RPH * 2) + part * 32;

    int l_r8 = lane & 7;
    int l_m1 = (lane >> 3) & 1;
    int l_m2 = lane >> 4;

    int gm = tid >> 3, ghc = tid & 7;
    int ghi = gm * Hd + c0 + ghc;
    const float* xpp = g_xproj + (size_t)gm * FourH + (c0 + ghc) * 4;

    float creg = 0.f;
    unsigned epoch = epoch0;

    // prefetch xp for t = 0
    float4 xp = *(const float4*)(xpp);

    for (int t = 0; t < Tlen; t++) {
        float acc[4][4];
#pragma unroll
        for (int mt = 0; mt < 4; mt++)
#pragma unroll
            for (int r = 0; r < 4; r++) acc[mt][r] = 0.f;

        if (t > 0) {
            const __half* hr_in = writeseq ? (seq + (size_t)(t - 1) * BHd)
                                           : ((t & 1) ? g_hr1 : g_hr0);
            const __half* hsrc = hr_in + srow * Hd + s * 256 + part * 16;

#pragma unroll
            for (int p = 0; p < 3; p++) {
                uint32_t dst = dbase + (p % NSTG) * KTF_B;
                cp16(dst,      hsrc + p * 32);
                cp16(dst + 16, hsrc + p * 32 + 8);
                cp_commit();
            }

#pragma unroll
            for (int kt = 0; kt < 8; kt++) {
                cp_wait<2>();
                bar_sync(1 + s, 128);
                if (kt + 3 < 8) {
                    uint32_t dst = dbase + ((kt + 3) % NSTG) * KTF_B;
                    cp16(dst,      hsrc + (kt + 3) * 32);
                    cp16(dst + 16, hsrc + (kt + 3) * 32 + 8);
                }
                cp_commit();

                uint32_t asb = sbase + (kt % NSTG) * KTF_B + s * RSEG_B;
#pragma unroll
                for (int kk = 0; kk < 2; kk++) {
                    int j = kt * 2 + kk;
                    int ak = kk * 16 + l_m2 * 8;
#pragma unroll
                    for (int mt = 0; mt < 4; mt++) {
                        int ar = mt * 16 + l_r8 + l_m1 * 8;
                        uint32_t a0, a1, a2, a3;
                        ldsm_x4(a0, a1, a2, a3, asb + (ar * RPH + ak) * 2);
                        mma_f16(acc[mt], a0, a1, a2, a3, b0[j], b1[j]);
                    }
                }
            }
        }

        // write k-split partials (per-warp private region)
#pragma unroll
        for (int mt = 0; mt < 4; mt++) {
            int row = mt * 16 + (lane >> 2);
            float* p = pD + s * PDSEG + row * PDPITCH + g * 8 + 2 * (lane & 3);
            p[0] = acc[mt][0];
            p[1] = acc[mt][1];
            p[8 * PDPITCH]     = acc[mt][2];
            p[8 * PDPITCH + 1] = acc[mt][3];
        }
        __syncthreads();

        // fused gate phase
        {
            float zi = xp.x, zf = xp.y, zg = xp.z, zo = xp.w;
#pragma unroll
            for (int spp = 0; spp < 4; spp++) {
                const float* q = pD + spp * PDSEG + gm * PDPITCH;
                zi += q[ghc];
                zf += q[8 + ghc];
                zg += q[16 + ghc];
                zo += q[24 + ghc];
            }
            float si = sigmoid_f(zi);
            float sf = sigmoid_f(zf);
            float so = sigmoid_f(zo);
            float tg = tanh_f(zg);
            float cn = sf * creg + si * tg;
            float hn = so * tanh_f(cn);
            creg = cn;
            __half hh = __float2half_rn(hn);
            if (writeseq) {
                seq[((size_t)(t * Bsz + gm)) * Hd + c0 + ghc] = hh;
            } else {
                __half* hr_out = (t & 1) ? g_hr0 : g_hr1;
                hr_out[ghi] = hh;
                if (t == Tlen - 1) g_hfull[ghi] = hn;
            }
        }

        // prefetch xp for t+1 — overlaps the grid barrier wait
        if (t + 1 < Tlen)
            xp = *(const float4*)(xpp + (size_t)(t + 1) * Bsz * FourH);

        grid_sync(++epoch);
    }
}

// ---------------- head ----------------
__global__ void head_kernel(const float* __restrict__ Wc, const float* __restrict__ bc,
                            float* __restrict__ out)
{
    int b = blockIdx.x;
    int w = threadIdx.x >> 5;
    int lane = threadIdx.x & 31;
    const float* h = g_hfull + b * Hd;
    float s = 0.f;
    for (int k = lane; k < Hd; k += 32) s += h[k] * Wc[k * Cd + w];
#pragma unroll
    for (int o = 16; o > 0; o >>= 1) s += __shfl_down_sync(0xffffffffu, s, o);
    if (lane == 0) out[b * Cd + w] = s + bc[w];
}

// ---------------- launch ----------------
extern "C" void kernel_launch(void* const* d_in, const int* in_sizes, int n_in,
                              void* d_out, int out_size)
{
    const float* x    = (const float*)d_in[0];
    const float* Wx0  = (const float*)d_in[1];
    const float* Wxs  = (const float*)d_in[2];
    const float* Whs  = (const float*)d_in[3];
    const float* bs   = (const float*)d_in[4];
    const float* Wc   = (const float*)d_in[5];
    const float* bc   = (const float*)d_in[6];
    float* out = (float*)d_out;

    cudaFuncSetAttribute(proj_gemm_tc,
                         cudaFuncAttributeMaxDynamicSharedMemorySize, PROJ_SMEM);
    cudaFuncSetAttribute(lstm_layer_tc,
                         cudaFuncAttributeMaxDynamicSharedMemorySize, REC_SMEM);

    __half* xh = nullptr; __half* wtf = nullptr;
    { void* p; cudaGetSymbolAddress(&p, g_xh); xh = (__half*)p; }
    { void* p; cudaGetSymbolAddress(&p, g_wtf); wtf = (__half*)p; }
    __half* hs0 = nullptr; __half* hs1 = nullptr;
    { void* p; cudaGetSymbolAddress(&p, g_hseq0); hs0 = (__half*)p; }
    { void* p; cudaGetSymbolAddress(&p, g_hseq1); hs1 = (__half*)p; }

    // prep: 2 launches (counter reset folded into preround_x)
    preround_x<<<512, 256>>>(x);
    transpose_all<<<dim3(FourH / 32, (Din + 4 * Hd) / 32), dim3(32, 8)>>>(Wx0, Wxs);

    dim3 pgrid(FourH / 256, Mrows / 128);   // 16 x 128

    for (int l = 0; l < Ld; l++) {
        const __half* A  = (l == 0) ? xh : (((l - 1) & 1) == 0 ? hs0 : hs1);
        const __half* Wt = (l == 0) ? wtf : (wtf + (size_t)Din * FourH
                                                + (size_t)(l - 1) * Hd * FourH);
        int K  = (l == 0) ? Din : Hd;
        int st = (l == 0) ? Din : Bsz * Hd;
        int sb = (l == 0) ? Tlen * Din : Hd;

        proj_gemm_tc<<<pgrid, 512, PROJ_SMEM>>>(A, st, sb, K, Wt,
                                                bs + (size_t)l * FourH);

        const float* Wh = Whs + (size_t)l * Hd * FourH;
        lstm_layer_tc<<<128, 512, REC_SMEM>>>(Wh, l & 1, (l < Ld - 1) ? 1 : 0,
                                              (unsigned)l * Tlen);
    }

    head_kernel<<<Bsz, 320>>>(Wc, bc, out);
}